// round 3
// baseline (speedup 1.0000x reference)
#include <cuda_runtime.h>
#include <math.h>

#define Nn 100000
#define Ee 1600000
#define Kin 128
#define Hh 4
#define Cc 64
#define Dd 256

// ---------------- scratch (device globals: no allocation allowed) ----------
__device__ float g_h[(size_t)Nn * Dd];     // 102.4 MB  projected features
__device__ float g_as[Nn * Hh];            // a_src per node/head
__device__ float g_ad[Nn * Hh];            // a_dst per node/head
__device__ int   g_deg[Nn];
__device__ int   g_off[Nn + 1];
__device__ int   g_cur[Nn];
__device__ int   g_csr[Ee];                // src node ids grouped by dst

// ---------------- packed fp32x2 helpers (sm_103a FFMA2 path) ---------------
__device__ __forceinline__ unsigned long long pack2(float v) {
    unsigned long long r;
    unsigned int b = __float_as_uint(v);
    asm("mov.b64 %0, {%1, %2};" : "=l"(r) : "r"(b), "r"(b));
    return r;
}
__device__ __forceinline__ void ffma2(unsigned long long& d,
                                      unsigned long long a,
                                      unsigned long long b) {
    asm("fma.rn.f32x2 %0, %1, %2, %0;" : "+l"(d) : "l"(a), "l"(b));
}
__device__ __forceinline__ void unpack2(unsigned long long v, float& lo, float& hi) {
    unsigned int a, b;
    asm("mov.b64 {%0, %1}, %2;" : "=r"(a), "=r"(b) : "l"(v));
    lo = __uint_as_float(a);
    hi = __uint_as_float(b);
}

// ---------------- GEMM + fused attention dots -------------------------------
__global__ __launch_bounds__(256, 2)
void gemm_att_kernel(const float* __restrict__ x, const float* __restrict__ W,
                     const float* __restrict__ att_src,
                     const float* __restrict__ att_dst) {
    __shared__ float As[16][128];   // [k][m]
    __shared__ float Bs[16][128];   // [k][n]
    const int m0 = blockIdx.x * 128;
    const int c0 = blockIdx.y * 128;
    const int tid = threadIdx.x;
    const int tx = tid & 15, ty = tid >> 4;

    unsigned long long acc[8][4];
    #pragma unroll
    for (int i = 0; i < 8; ++i)
        #pragma unroll
        for (int j = 0; j < 4; ++j) acc[i][j] = 0ull;

    const int f0 = tid * 2, f1 = tid * 2 + 1;
    const int ar0 = f0 >> 2, ak0 = (f0 & 3) * 4;
    const int ar1 = f1 >> 2, ak1 = (f1 & 3) * 4;
    const int bk0 = f0 >> 5, bn0 = (f0 & 31) * 4;
    const int bk1 = f1 >> 5, bn1 = (f1 & 31) * 4;

    for (int kt = 0; kt < 8; ++kt) {
        const int k0 = kt * 16;
        float4 av0 = make_float4(0.f, 0.f, 0.f, 0.f), av1 = av0;
        if (m0 + ar0 < Nn) av0 = *(const float4*)(x + (size_t)(m0 + ar0) * Kin + k0 + ak0);
        if (m0 + ar1 < Nn) av1 = *(const float4*)(x + (size_t)(m0 + ar1) * Kin + k0 + ak1);
        float4 bv0 = *(const float4*)(W + (size_t)(k0 + bk0) * Dd + c0 + bn0);
        float4 bv1 = *(const float4*)(W + (size_t)(k0 + bk1) * Dd + c0 + bn1);

        __syncthreads();
        As[ak0 + 0][ar0] = av0.x; As[ak0 + 1][ar0] = av0.y;
        As[ak0 + 2][ar0] = av0.z; As[ak0 + 3][ar0] = av0.w;
        As[ak1 + 0][ar1] = av1.x; As[ak1 + 1][ar1] = av1.y;
        As[ak1 + 2][ar1] = av1.z; As[ak1 + 3][ar1] = av1.w;
        *(float4*)&Bs[bk0][bn0] = bv0;
        *(float4*)&Bs[bk1][bn1] = bv1;
        __syncthreads();

        #pragma unroll
        for (int k = 0; k < 16; ++k) {
            const float4 a0 = *(const float4*)&As[k][ty * 8];
            const float4 a1 = *(const float4*)&As[k][ty * 8 + 4];
            const ulonglong2 b0 = *(const ulonglong2*)&Bs[k][tx * 8];
            const ulonglong2 b1 = *(const ulonglong2*)&Bs[k][tx * 8 + 4];
            float a[8] = {a0.x, a0.y, a0.z, a0.w, a1.x, a1.y, a1.z, a1.w};
            #pragma unroll
            for (int m = 0; m < 8; ++m) {
                unsigned long long ap = pack2(a[m]);
                ffma2(acc[m][0], ap, b0.x);
                ffma2(acc[m][1], ap, b0.y);
                ffma2(acc[m][2], ap, b1.x);
                ffma2(acc[m][3], ap, b1.y);
            }
        }
    }

    const int head = blockIdx.y * 2 + (tx >> 3);
    const int cin0 = (tx & 7) * 8;
    float asv[8], adv[8];
    #pragma unroll
    for (int j = 0; j < 8; ++j) {
        asv[j] = att_src[head * 64 + cin0 + j];
        adv[j] = att_dst[head * 64 + cin0 + j];
    }

    #pragma unroll
    for (int m = 0; m < 8; ++m) {
        const int row = m0 + ty * 8 + m;
        float v[8];
        unpack2(acc[m][0], v[0], v[1]);
        unpack2(acc[m][1], v[2], v[3]);
        unpack2(acc[m][2], v[4], v[5]);
        unpack2(acc[m][3], v[6], v[7]);
        if (row < Nn) {
            float* hp = g_h + (size_t)row * Dd + c0 + tx * 8;
            *(float4*)hp = make_float4(v[0], v[1], v[2], v[3]);
            *(float4*)(hp + 4) = make_float4(v[4], v[5], v[6], v[7]);
        }
        float ss = 0.f, sd = 0.f;
        #pragma unroll
        for (int j = 0; j < 8; ++j) { ss += v[j] * asv[j]; sd += v[j] * adv[j]; }
        #pragma unroll
        for (int o = 4; o; o >>= 1) {
            ss += __shfl_xor_sync(0xffffffffu, ss, o);
            sd += __shfl_xor_sync(0xffffffffu, sd, o);
        }
        if ((tx & 7) == 0 && row < Nn) {
            g_as[row * 4 + head] = ss;
            g_ad[row * 4 + head] = sd;
        }
    }
}

// ---------------- CSR build -------------------------------------------------
__global__ void degree_kernel(const int* __restrict__ ei) {
    int e = blockIdx.x * blockDim.x + threadIdx.x;
    if (e < Ee) atomicAdd(&g_deg[ei[Ee + e]], 1);
}

__global__ void scan_kernel() {
    __shared__ int ssum[1024];
    const int t = threadIdx.x;
    const int C = 98;  // 1024*98 >= 100000
    int base = t * C;
    int s = 0;
    for (int j = 0; j < C; ++j) {
        int idx = base + j;
        if (idx < Nn) s += g_deg[idx];
    }
    ssum[t] = s;
    __syncthreads();
    for (int off = 1; off < 1024; off <<= 1) {
        int add = (t >= off) ? ssum[t - off] : 0;
        __syncthreads();
        ssum[t] += add;
        __syncthreads();
    }
    int run = (t == 0) ? 0 : ssum[t - 1];
    for (int j = 0; j < C; ++j) {
        int idx = base + j;
        if (idx < Nn) {
            g_off[idx] = run;
            g_cur[idx] = run;
            run += g_deg[idx];
        }
    }
    if (t == 1023) g_off[Nn] = ssum[1023];
}

__global__ void scatter_kernel(const int* __restrict__ ei) {
    int e = blockIdx.x * blockDim.x + threadIdx.x;
    if (e >= Ee) return;
    int s = ei[e];
    int d = ei[Ee + e];
    int pos = atomicAdd(&g_cur[d], 1);
    g_csr[pos] = s;
}

// ---------------- fused gather: softmax + aggregate + ELU + LayerNorm ------
__device__ __forceinline__ float lrelu(float v) {
    return v > 0.f ? v : 0.2f * v;
}
__device__ __forceinline__ void onl(float l, float& m, float& s) {
    if (l > m) { s = s * __expf(m - l) + 1.f; m = l; }
    else       { s += __expf(l - m); }
}
__device__ __forceinline__ void comb(float& m, float& s, float mo, float so) {
    float mm = fmaxf(m, mo);
    s = s * __expf(m - mm) + so * __expf(mo - mm);
    m = mm;
}

__global__ void gather_kernel(const float* __restrict__ bias,
                              const float* __restrict__ gamma,
                              const float* __restrict__ beta,
                              float* __restrict__ out) {
    const int w = threadIdx.x >> 5;
    const int lane = threadIdx.x & 31;
    const int n = blockIdx.x * 8 + w;
    if (n >= Nn) return;

    const float4 ad4 = *(const float4*)(g_ad + n * 4);
    const float4 own_as4 = *(const float4*)(g_as + n * 4);
    const int off0 = g_off[n], off1 = g_off[n + 1];

    // ---- pass 1: softmax stats per head (distributed over lanes) ----
    float m0 = -1e30f, m1 = -1e30f, m2 = -1e30f, m3 = -1e30f;
    float s0 = 0.f, s1 = 0.f, s2 = 0.f, s3 = 0.f;
    if (lane == 0) {  // self loop contribution
        onl(lrelu(own_as4.x + ad4.x), m0, s0);
        onl(lrelu(own_as4.y + ad4.y), m1, s1);
        onl(lrelu(own_as4.z + ad4.z), m2, s2);
        onl(lrelu(own_as4.w + ad4.w), m3, s3);
    }
    for (int i = off0 + lane; i < off1; i += 32) {
        int src = g_csr[i];
        float4 as4 = *(const float4*)(g_as + src * 4);
        onl(lrelu(as4.x + ad4.x), m0, s0);
        onl(lrelu(as4.y + ad4.y), m1, s1);
        onl(lrelu(as4.z + ad4.z), m2, s2);
        onl(lrelu(as4.w + ad4.w), m3, s3);
    }
    #pragma unroll
    for (int o = 16; o; o >>= 1) {
        float mo, so;
        mo = __shfl_xor_sync(0xffffffffu, m0, o); so = __shfl_xor_sync(0xffffffffu, s0, o); comb(m0, s0, mo, so);
        mo = __shfl_xor_sync(0xffffffffu, m1, o); so = __shfl_xor_sync(0xffffffffu, s1, o); comb(m1, s1, mo, so);
        mo = __shfl_xor_sync(0xffffffffu, m2, o); so = __shfl_xor_sync(0xffffffffu, s2, o); comb(m2, s2, mo, so);
        mo = __shfl_xor_sync(0xffffffffu, m3, o); so = __shfl_xor_sync(0xffffffffu, s3, o); comb(m3, s3, mo, so);
    }

    // per-head max/denominator, kept on all lanes
    const float mx[4] = {m0, m1, m2, m3};
    const float rd[4] = {1.f / s0, 1.f / s1, 1.f / s2, 1.f / s3};
    const float adv[4] = {ad4.x, ad4.y, ad4.z, ad4.w};

    // lane owns channels [lane*4,+4) (head A = lane/16) and [128+lane*4,+4) (head B)
    const int hA = lane >> 4, hB = 2 + (lane >> 4);

    // ---- pass 2: weighted aggregation, 4 edges per chunk ----
    float4 acc0, acc1;
    {   // self loop first
        float aA = __expf(lrelu((hA == 0 ? own_as4.x : own_as4.y) + adv[hA]) - mx[hA]) * rd[hA];
        float aB = __expf(lrelu((hA == 0 ? own_as4.z : own_as4.w) + adv[hB]) - mx[hB]) * rd[hB];
        const float4* hp = (const float4*)(g_h + (size_t)n * Dd);
        float4 h0 = hp[lane];
        float4 h1 = hp[32 + lane];
        acc0 = make_float4(h0.x * aA, h0.y * aA, h0.z * aA, h0.w * aA);
        acc1 = make_float4(h1.x * aB, h1.y * aB, h1.z * aB, h1.w * aB);
    }

    for (int base = off0; base < off1; base += 4) {
        const int nb = min(4, off1 - base);
        // lanes 0..nb-1 load csr + a_src and compute all 4 head alphas
        int src_l = n;
        float al0 = 0.f, al1 = 0.f, al2 = 0.f, al3 = 0.f;
        if (lane < nb) {
            src_l = g_csr[base + lane];
            float4 as4 = *(const float4*)(g_as + src_l * 4);
            al0 = __expf(lrelu(as4.x + adv[0]) - mx[0]) * rd[0];
            al1 = __expf(lrelu(as4.y + adv[1]) - mx[1]) * rd[1];
            al2 = __expf(lrelu(as4.z + adv[2]) - mx[2]) * rd[2];
            al3 = __expf(lrelu(as4.w + adv[3]) - mx[3]) * rd[3];
        }

        float4 h0[4], h1[4];
        float aA[4], aB[4];
        #pragma unroll
        for (int j = 0; j < 4; ++j) {
            if (j < nb) {
                int src = __shfl_sync(0xffffffffu, src_l, j);
                float a0 = __shfl_sync(0xffffffffu, al0, j);
                float a1 = __shfl_sync(0xffffffffu, al1, j);
                float a2 = __shfl_sync(0xffffffffu, al2, j);
                float a3 = __shfl_sync(0xffffffffu, al3, j);
                aA[j] = (hA == 0) ? a0 : a1;
                aB[j] = (hA == 0) ? a2 : a3;
                const float4* hp = (const float4*)(g_h + (size_t)src * Dd);
                h0[j] = hp[lane];
                h1[j] = hp[32 + lane];
            } else {
                aA[j] = 0.f; aB[j] = 0.f;
                h0[j] = make_float4(0.f, 0.f, 0.f, 0.f);
                h1[j] = h0[j];
            }
        }
        #pragma unroll
        for (int j = 0; j < 4; ++j) {
            acc0.x += h0[j].x * aA[j]; acc0.y += h0[j].y * aA[j];
            acc0.z += h0[j].z * aA[j]; acc0.w += h0[j].w * aA[j];
            acc1.x += h1[j].x * aB[j]; acc1.y += h1[j].y * aB[j];
            acc1.z += h1[j].z * aB[j]; acc1.w += h1[j].w * aB[j];
        }
    }

    // ---- epilogue: bias + ELU + LayerNorm ----
    const float4 b0 = ((const float4*)bias)[lane];
    const float4 b1 = ((const float4*)bias)[32 + lane];
    float v[8];
    v[0] = acc0.x + b0.x; v[1] = acc0.y + b0.y; v[2] = acc0.z + b0.z; v[3] = acc0.w + b0.w;
    v[4] = acc1.x + b1.x; v[5] = acc1.y + b1.y; v[6] = acc1.z + b1.z; v[7] = acc1.w + b1.w;
    float sum = 0.f, sq = 0.f;
    #pragma unroll
    for (int j = 0; j < 8; ++j) {
        v[j] = v[j] > 0.f ? v[j] : expm1f(v[j]);
        sum += v[j];
        sq += v[j] * v[j];
    }
    #pragma unroll
    for (int o = 16; o; o >>= 1) {
        sum += __shfl_xor_sync(0xffffffffu, sum, o);
        sq  += __shfl_xor_sync(0xffffffffu, sq, o);
    }
    const float mean = sum * (1.f / 256.f);
    const float var = sq * (1.f / 256.f) - mean * mean;
    const float rstd = rsqrtf(var + 1e-5f);

    const float4 g0 = ((const float4*)gamma)[lane];
    const float4 g1 = ((const float4*)gamma)[32 + lane];
    const float4 be0 = ((const float4*)beta)[lane];
    const float4 be1 = ((const float4*)beta)[32 + lane];
    float4 o0, o1;
    o0.x = (v[0] - mean) * rstd * g0.x + be0.x;
    o0.y = (v[1] - mean) * rstd * g0.y + be0.y;
    o0.z = (v[2] - mean) * rstd * g0.z + be0.z;
    o0.w = (v[3] - mean) * rstd * g0.w + be0.w;
    o1.x = (v[4] - mean) * rstd * g1.x + be1.x;
    o1.y = (v[5] - mean) * rstd * g1.y + be1.y;
    o1.z = (v[6] - mean) * rstd * g1.z + be1.z;
    o1.w = (v[7] - mean) * rstd * g1.w + be1.w;
    float4* op = (float4*)(out + (size_t)n * Dd);
    op[lane] = o0;
    op[32 + lane] = o1;
}

// ---------------- stream/event singletons (created at load, outside capture)
namespace {
struct GpuRes {
    cudaStream_t s2;
    cudaEvent_t evF, evJ;
    GpuRes() {
        cudaStreamCreateWithFlags(&s2, cudaStreamNonBlocking);
        cudaEventCreateWithFlags(&evF, cudaEventDisableTiming);
        cudaEventCreateWithFlags(&evJ, cudaEventDisableTiming);
    }
};
GpuRes g_res;
}

// ---------------------------------------------------------------------------
extern "C" void kernel_launch(void* const* d_in, const int* in_sizes, int n_in,
                              void* d_out, int out_size) {
    const float* x = (const float*)d_in[0];
    const int* ei = (const int*)d_in[1];
    const float* W = (const float*)d_in[2];
    const float* att_src = (const float*)d_in[3];
    const float* att_dst = (const float*)d_in[4];
    const float* bias = (const float*)d_in[5];
    const float* gamma = (const float*)d_in[6];
    const float* beta = (const float*)d_in[7];
    float* out = (float*)d_out;

    void* degPtr = nullptr;
    cudaGetSymbolAddress(&degPtr, g_deg);

    // fork: CSR build on side stream, concurrent with GEMM on main stream
    cudaEventRecord(g_res.evF, 0);
    cudaStreamWaitEvent(g_res.s2, g_res.evF, 0);
    cudaMemsetAsync(degPtr, 0, Nn * sizeof(int), g_res.s2);
    degree_kernel<<<(Ee + 255) / 256, 256, 0, g_res.s2>>>(ei);
    scan_kernel<<<1, 1024, 0, g_res.s2>>>();
    scatter_kernel<<<(Ee + 255) / 256, 256, 0, g_res.s2>>>(ei);
    cudaEventRecord(g_res.evJ, g_res.s2);

    gemm_att_kernel<<<dim3((Nn + 127) / 128, Dd / 128), 256>>>(x, W, att_src, att_dst);

    // join, then fused gather
    cudaStreamWaitEvent(0, g_res.evJ, 0);
    gather_kernel<<<(Nn + 7) / 8, 256>>>(bias, gamma, beta, out);
}

// round 4
// speedup vs baseline: 1.1682x; 1.1682x over previous
#include <cuda_runtime.h>
#include <cuda_fp16.h>
#include <math.h>

#define Nn 100000
#define Ee 1600000
#define Kin 128
#define Hh 4
#define Cc 64
#define Dd 256

// ---------------- scratch (device globals: no allocation allowed) ----------
__device__ __half g_h16[(size_t)Nn * Dd];  // 51.2 MB projected features (fp16)
__device__ float g_as[Nn * Hh];            // a_src per node/head (fp32, exact)
__device__ float g_ad[Nn * Hh];            // a_dst per node/head
__device__ int   g_deg[Nn];
__device__ int   g_off[Nn + 1];
__device__ int   g_cur[Nn];
__device__ int   g_csr[Ee];                // src node ids grouped by dst

// ---------------- packed fp32x2 helpers (sm_103a FFMA2 path) ---------------
__device__ __forceinline__ unsigned long long pack2(float v) {
    unsigned long long r;
    unsigned int b = __float_as_uint(v);
    asm("mov.b64 %0, {%1, %2};" : "=l"(r) : "r"(b), "r"(b));
    return r;
}
__device__ __forceinline__ void ffma2(unsigned long long& d,
                                      unsigned long long a,
                                      unsigned long long b) {
    asm("fma.rn.f32x2 %0, %1, %2, %0;" : "+l"(d) : "l"(a), "l"(b));
}
__device__ __forceinline__ void unpack2(unsigned long long v, float& lo, float& hi) {
    unsigned int a, b;
    asm("mov.b64 {%0, %1}, %2;" : "=r"(a), "=r"(b) : "l"(v));
    lo = __uint_as_float(a);
    hi = __uint_as_float(b);
}

// ---------------- GEMM + fused attention dots -------------------------------
// g_h16 = fp16(x @ W); g_as/g_ad from fp32 accumulators (exact).
__global__ __launch_bounds__(256, 2)
void gemm_att_kernel(const float* __restrict__ x, const float* __restrict__ W,
                     const float* __restrict__ att_src,
                     const float* __restrict__ att_dst) {
    __shared__ float As[16][128];   // [k][m]
    __shared__ float Bs[16][128];   // [k][n]
    const int m0 = blockIdx.x * 128;
    const int c0 = blockIdx.y * 128;
    const int tid = threadIdx.x;
    const int tx = tid & 15, ty = tid >> 4;

    unsigned long long acc[8][4];
    #pragma unroll
    for (int i = 0; i < 8; ++i)
        #pragma unroll
        for (int j = 0; j < 4; ++j) acc[i][j] = 0ull;

    const int f0 = tid * 2, f1 = tid * 2 + 1;
    const int ar0 = f0 >> 2, ak0 = (f0 & 3) * 4;
    const int ar1 = f1 >> 2, ak1 = (f1 & 3) * 4;
    const int bk0 = f0 >> 5, bn0 = (f0 & 31) * 4;
    const int bk1 = f1 >> 5, bn1 = (f1 & 31) * 4;

    for (int kt = 0; kt < 8; ++kt) {
        const int k0 = kt * 16;
        float4 av0 = make_float4(0.f, 0.f, 0.f, 0.f), av1 = av0;
        if (m0 + ar0 < Nn) av0 = *(const float4*)(x + (size_t)(m0 + ar0) * Kin + k0 + ak0);
        if (m0 + ar1 < Nn) av1 = *(const float4*)(x + (size_t)(m0 + ar1) * Kin + k0 + ak1);
        float4 bv0 = *(const float4*)(W + (size_t)(k0 + bk0) * Dd + c0 + bn0);
        float4 bv1 = *(const float4*)(W + (size_t)(k0 + bk1) * Dd + c0 + bn1);

        __syncthreads();
        As[ak0 + 0][ar0] = av0.x; As[ak0 + 1][ar0] = av0.y;
        As[ak0 + 2][ar0] = av0.z; As[ak0 + 3][ar0] = av0.w;
        As[ak1 + 0][ar1] = av1.x; As[ak1 + 1][ar1] = av1.y;
        As[ak1 + 2][ar1] = av1.z; As[ak1 + 3][ar1] = av1.w;
        *(float4*)&Bs[bk0][bn0] = bv0;
        *(float4*)&Bs[bk1][bn1] = bv1;
        __syncthreads();

        #pragma unroll
        for (int k = 0; k < 16; ++k) {
            const float4 a0 = *(const float4*)&As[k][ty * 8];
            const float4 a1 = *(const float4*)&As[k][ty * 8 + 4];
            const ulonglong2 b0 = *(const ulonglong2*)&Bs[k][tx * 8];
            const ulonglong2 b1 = *(const ulonglong2*)&Bs[k][tx * 8 + 4];
            float a[8] = {a0.x, a0.y, a0.z, a0.w, a1.x, a1.y, a1.z, a1.w};
            #pragma unroll
            for (int m = 0; m < 8; ++m) {
                unsigned long long ap = pack2(a[m]);
                ffma2(acc[m][0], ap, b0.x);
                ffma2(acc[m][1], ap, b0.y);
                ffma2(acc[m][2], ap, b1.x);
                ffma2(acc[m][3], ap, b1.y);
            }
        }
    }

    const int head = blockIdx.y * 2 + (tx >> 3);
    const int cin0 = (tx & 7) * 8;
    float asv[8], adv[8];
    #pragma unroll
    for (int j = 0; j < 8; ++j) {
        asv[j] = att_src[head * 64 + cin0 + j];
        adv[j] = att_dst[head * 64 + cin0 + j];
    }

    #pragma unroll
    for (int m = 0; m < 8; ++m) {
        const int row = m0 + ty * 8 + m;
        float v[8];
        unpack2(acc[m][0], v[0], v[1]);
        unpack2(acc[m][1], v[2], v[3]);
        unpack2(acc[m][2], v[4], v[5]);
        unpack2(acc[m][3], v[6], v[7]);
        if (row < Nn) {
            __half2 p0 = __floats2half2_rn(v[0], v[1]);
            __half2 p1 = __floats2half2_rn(v[2], v[3]);
            __half2 p2 = __floats2half2_rn(v[4], v[5]);
            __half2 p3 = __floats2half2_rn(v[6], v[7]);
            uint4 hv;
            hv.x = *(unsigned int*)&p0;
            hv.y = *(unsigned int*)&p1;
            hv.z = *(unsigned int*)&p2;
            hv.w = *(unsigned int*)&p3;
            *(uint4*)(g_h16 + (size_t)row * Dd + c0 + tx * 8) = hv;
        }
        float ss = 0.f, sd = 0.f;
        #pragma unroll
        for (int j = 0; j < 8; ++j) { ss += v[j] * asv[j]; sd += v[j] * adv[j]; }
        #pragma unroll
        for (int o = 4; o; o >>= 1) {
            ss += __shfl_xor_sync(0xffffffffu, ss, o);
            sd += __shfl_xor_sync(0xffffffffu, sd, o);
        }
        if ((tx & 7) == 0 && row < Nn) {
            g_as[row * 4 + head] = ss;
            g_ad[row * 4 + head] = sd;
        }
    }
}

// ---------------- CSR build -------------------------------------------------
__global__ void degree_kernel(const int* __restrict__ ei) {
    int e = blockIdx.x * blockDim.x + threadIdx.x;
    if (e < Ee) atomicAdd(&g_deg[ei[Ee + e]], 1);
}

__global__ void scan_kernel() {
    __shared__ int ssum[1024];
    const int t = threadIdx.x;
    const int C = 98;  // 1024*98 >= 100000
    int base = t * C;
    int s = 0;
    for (int j = 0; j < C; ++j) {
        int idx = base + j;
        if (idx < Nn) s += g_deg[idx];
    }
    ssum[t] = s;
    __syncthreads();
    for (int off = 1; off < 1024; off <<= 1) {
        int add = (t >= off) ? ssum[t - off] : 0;
        __syncthreads();
        ssum[t] += add;
        __syncthreads();
    }
    int run = (t == 0) ? 0 : ssum[t - 1];
    for (int j = 0; j < C; ++j) {
        int idx = base + j;
        if (idx < Nn) {
            g_off[idx] = run;
            g_cur[idx] = run;
            run += g_deg[idx];
        }
    }
    if (t == 1023) g_off[Nn] = ssum[1023];
}

__global__ void scatter_kernel(const int* __restrict__ ei) {
    int e = blockIdx.x * blockDim.x + threadIdx.x;
    if (e >= Ee) return;
    int s = ei[e];
    int d = ei[Ee + e];
    int pos = atomicAdd(&g_cur[d], 1);
    g_csr[pos] = s;
}

// ---------------- fused gather: softmax + aggregate + ELU + LayerNorm ------
__device__ __forceinline__ float lrelu(float v) {
    return v > 0.f ? v : 0.2f * v;
}
__device__ __forceinline__ void onl(float l, float& m, float& s) {
    if (l > m) { s = s * __expf(m - l) + 1.f; m = l; }
    else       { s += __expf(l - m); }
}
__device__ __forceinline__ void comb(float& m, float& s, float mo, float so) {
    float mm = fmaxf(m, mo);
    s = s * __expf(m - mm) + so * __expf(mo - mm);
    m = mm;
}
__device__ __forceinline__ float selh(const float4& v, int h) {
    return h == 0 ? v.x : (h == 1 ? v.y : (h == 2 ? v.z : v.w));
}
__device__ __forceinline__ void accum8(float* acc, const uint4& hv, float a) {
    float2 f;
    f = __half22float2(*(const __half2*)&hv.x); acc[0] += f.x * a; acc[1] += f.y * a;
    f = __half22float2(*(const __half2*)&hv.y); acc[2] += f.x * a; acc[3] += f.y * a;
    f = __half22float2(*(const __half2*)&hv.z); acc[4] += f.x * a; acc[5] += f.y * a;
    f = __half22float2(*(const __half2*)&hv.w); acc[6] += f.x * a; acc[7] += f.y * a;
}

__global__ void gather_kernel(const float* __restrict__ bias,
                              const float* __restrict__ gamma,
                              const float* __restrict__ beta,
                              float* __restrict__ out) {
    const int w = threadIdx.x >> 5;
    const int lane = threadIdx.x & 31;
    const int n = blockIdx.x * 8 + w;
    if (n >= Nn) return;

    const float4 ad4 = *(const float4*)(g_ad + n * 4);
    const float4 own_as4 = *(const float4*)(g_as + n * 4);
    const int off0 = g_off[n], off1 = g_off[n + 1];

    // ---- pass 1: softmax stats per head (distributed over lanes) ----
    float m0 = -1e30f, m1 = -1e30f, m2 = -1e30f, m3 = -1e30f;
    float s0 = 0.f, s1 = 0.f, s2 = 0.f, s3 = 0.f;
    if (lane == 0) {  // self loop
        onl(lrelu(own_as4.x + ad4.x), m0, s0);
        onl(lrelu(own_as4.y + ad4.y), m1, s1);
        onl(lrelu(own_as4.z + ad4.z), m2, s2);
        onl(lrelu(own_as4.w + ad4.w), m3, s3);
    }
    for (int i = off0 + lane; i < off1; i += 32) {
        int src = g_csr[i];
        float4 as4 = *(const float4*)(g_as + src * 4);
        onl(lrelu(as4.x + ad4.x), m0, s0);
        onl(lrelu(as4.y + ad4.y), m1, s1);
        onl(lrelu(as4.z + ad4.z), m2, s2);
        onl(lrelu(as4.w + ad4.w), m3, s3);
    }
    #pragma unroll
    for (int o = 16; o; o >>= 1) {
        float mo, so;
        mo = __shfl_xor_sync(0xffffffffu, m0, o); so = __shfl_xor_sync(0xffffffffu, s0, o); comb(m0, s0, mo, so);
        mo = __shfl_xor_sync(0xffffffffu, m1, o); so = __shfl_xor_sync(0xffffffffu, s1, o); comb(m1, s1, mo, so);
        mo = __shfl_xor_sync(0xffffffffu, m2, o); so = __shfl_xor_sync(0xffffffffu, s2, o); comb(m2, s2, mo, so);
        mo = __shfl_xor_sync(0xffffffffu, m3, o); so = __shfl_xor_sync(0xffffffffu, s3, o); comb(m3, s3, mo, so);
    }

    // lane owns 8 channels [lane*8, +8) -> exactly one head: lane>>3
    const int hL = lane >> 3;
    float mxL, rdL, advL;
    {
        const float mx[4] = {m0, m1, m2, m3};
        const float rd[4] = {1.f / s0, 1.f / s1, 1.f / s2, 1.f / s3};
        const float adv[4] = {ad4.x, ad4.y, ad4.z, ad4.w};
        mxL = mx[hL]; rdL = rd[hL]; advL = adv[hL];
    }
    const __half* hbase = g_h16;
    const size_t laneoff = (size_t)lane * 8;

    float acc[8] = {0.f, 0.f, 0.f, 0.f, 0.f, 0.f, 0.f, 0.f};
    {   // self loop
        float al = __expf(lrelu(selh(own_as4, hL) + advL) - mxL) * rdL;
        uint4 hv = *(const uint4*)(hbase + (size_t)n * Dd + laneoff);
        accum8(acc, hv, al);
    }

    // ---- pass 2: 4-edge batches, loads issued up front (no shfl) ----
    int i = off0;
    for (; i + 4 <= off1; i += 4) {
        const int s0i = g_csr[i], s1i = g_csr[i + 1];
        const int s2i = g_csr[i + 2], s3i = g_csr[i + 3];
        const float4 p0 = *(const float4*)(g_as + s0i * 4);
        const float4 p1 = *(const float4*)(g_as + s1i * 4);
        const float4 p2 = *(const float4*)(g_as + s2i * 4);
        const float4 p3 = *(const float4*)(g_as + s3i * 4);
        const uint4 v0 = *(const uint4*)(hbase + (size_t)s0i * Dd + laneoff);
        const uint4 v1 = *(const uint4*)(hbase + (size_t)s1i * Dd + laneoff);
        const uint4 v2 = *(const uint4*)(hbase + (size_t)s2i * Dd + laneoff);
        const uint4 v3 = *(const uint4*)(hbase + (size_t)s3i * Dd + laneoff);
        const float a0 = __expf(lrelu(selh(p0, hL) + advL) - mxL) * rdL;
        const float a1 = __expf(lrelu(selh(p1, hL) + advL) - mxL) * rdL;
        const float a2 = __expf(lrelu(selh(p2, hL) + advL) - mxL) * rdL;
        const float a3 = __expf(lrelu(selh(p3, hL) + advL) - mxL) * rdL;
        accum8(acc, v0, a0);
        accum8(acc, v1, a1);
        accum8(acc, v2, a2);
        accum8(acc, v3, a3);
    }
    for (; i < off1; ++i) {
        const int src = g_csr[i];
        const float4 p = *(const float4*)(g_as + src * 4);
        const uint4 v = *(const uint4*)(hbase + (size_t)src * Dd + laneoff);
        const float a = __expf(lrelu(selh(p, hL) + advL) - mxL) * rdL;
        accum8(acc, v, a);
    }

    // ---- epilogue: bias + ELU + LayerNorm ----
    const float4 b0 = *(const float4*)(bias + lane * 8);
    const float4 b1 = *(const float4*)(bias + lane * 8 + 4);
    float v[8];
    v[0] = acc[0] + b0.x; v[1] = acc[1] + b0.y; v[2] = acc[2] + b0.z; v[3] = acc[3] + b0.w;
    v[4] = acc[4] + b1.x; v[5] = acc[5] + b1.y; v[6] = acc[6] + b1.z; v[7] = acc[7] + b1.w;
    float sum = 0.f, sq = 0.f;
    #pragma unroll
    for (int j = 0; j < 8; ++j) {
        v[j] = v[j] > 0.f ? v[j] : expm1f(v[j]);
        sum += v[j];
        sq += v[j] * v[j];
    }
    #pragma unroll
    for (int o = 16; o; o >>= 1) {
        sum += __shfl_xor_sync(0xffffffffu, sum, o);
        sq  += __shfl_xor_sync(0xffffffffu, sq, o);
    }
    const float mean = sum * (1.f / 256.f);
    const float var = sq * (1.f / 256.f) - mean * mean;
    const float rstd = rsqrtf(var + 1e-5f);

    const float4 g0 = *(const float4*)(gamma + lane * 8);
    const float4 g1 = *(const float4*)(gamma + lane * 8 + 4);
    const float4 be0 = *(const float4*)(beta + lane * 8);
    const float4 be1 = *(const float4*)(beta + lane * 8 + 4);
    float4 o0, o1;
    o0.x = (v[0] - mean) * rstd * g0.x + be0.x;
    o0.y = (v[1] - mean) * rstd * g0.y + be0.y;
    o0.z = (v[2] - mean) * rstd * g0.z + be0.z;
    o0.w = (v[3] - mean) * rstd * g0.w + be0.w;
    o1.x = (v[4] - mean) * rstd * g1.x + be1.x;
    o1.y = (v[5] - mean) * rstd * g1.y + be1.y;
    o1.z = (v[6] - mean) * rstd * g1.z + be1.z;
    o1.w = (v[7] - mean) * rstd * g1.w + be1.w;
    // streaming stores: keep h resident in L2
    __stcs((float4*)(out + (size_t)n * Dd + lane * 8), o0);
    __stcs((float4*)(out + (size_t)n * Dd + lane * 8 + 4), o1);
}

// ---------------- stream/event singletons (created at load, outside capture)
namespace {
struct GpuRes {
    cudaStream_t s2;
    cudaEvent_t evF, evJ;
    GpuRes() {
        cudaStreamCreateWithFlags(&s2, cudaStreamNonBlocking);
        cudaEventCreateWithFlags(&evF, cudaEventDisableTiming);
        cudaEventCreateWithFlags(&evJ, cudaEventDisableTiming);
    }
};
GpuRes g_res;
}

// ---------------------------------------------------------------------------
extern "C" void kernel_launch(void* const* d_in, const int* in_sizes, int n_in,
                              void* d_out, int out_size) {
    const float* x = (const float*)d_in[0];
    const int* ei = (const int*)d_in[1];
    const float* W = (const float*)d_in[2];
    const float* att_src = (const float*)d_in[3];
    const float* att_dst = (const float*)d_in[4];
    const float* bias = (const float*)d_in[5];
    const float* gamma = (const float*)d_in[6];
    const float* beta = (const float*)d_in[7];
    float* out = (float*)d_out;

    void* degPtr = nullptr;
    cudaGetSymbolAddress(&degPtr, g_deg);

    // fork: CSR build on side stream, concurrent with GEMM on main stream
    cudaEventRecord(g_res.evF, 0);
    cudaStreamWaitEvent(g_res.s2, g_res.evF, 0);
    cudaMemsetAsync(degPtr, 0, Nn * sizeof(int), g_res.s2);
    degree_kernel<<<(Ee + 255) / 256, 256, 0, g_res.s2>>>(ei);
    scan_kernel<<<1, 1024, 0, g_res.s2>>>();
    scatter_kernel<<<(Ee + 255) / 256, 256, 0, g_res.s2>>>(ei);
    cudaEventRecord(g_res.evJ, g_res.s2);

    gemm_att_kernel<<<dim3((Nn + 127) / 128, Dd / 128), 256>>>(x, W, att_src, att_dst);

    // join, then fused gather
    cudaStreamWaitEvent(0, g_res.evJ, 0);
    gather_kernel<<<(Nn + 7) / 8, 256>>>(bias, gamma, beta, out);
}